// round 1
// baseline (speedup 1.0000x reference)
#include <cuda_runtime.h>
#include <cstdint>
#include <cstddef>

// Problem constants
#define N_HEADS 16
#define BATCH   4
#define SEQ     2048
#define CDIM    1024
#define HDIM    64
#define MROWS   (BATCH * SEQ)   // 8192

// ---------------------------------------------------------------------------
// Scratch (device globals: allocation-free rule)
// ---------------------------------------------------------------------------
__device__ float g_Q[(size_t)MROWS * CDIM];
__device__ float g_K[(size_t)MROWS * CDIM];
__device__ float g_V[(size_t)MROWS * CDIM];
__device__ float g_Y[(size_t)MROWS * CDIM];

// ---------------------------------------------------------------------------
// tf32 helper: round-to-nearest conversion (truncation would bias dot
// products low by ~1e-3 over K=1024 and fail the tolerance)
// ---------------------------------------------------------------------------
__device__ __forceinline__ uint32_t f2tf32(float x) {
    uint32_t r;
    asm("cvt.rna.tf32.f32 %0, %1;" : "=r"(r) : "f"(x));
    return r;
}

// ---------------------------------------------------------------------------
// GEMM: C[M,N] = A[M,K] @ W[K,N] + bias[N]   (fp32 gmem, tf32 MMA, fp32 accum)
// BM=128 BN=128 BK=16, 256 threads, warp grid 4(M) x 2(N), warp tile 32x64
// ---------------------------------------------------------------------------
#define BM 128
#define BN 128
#define BKK 16
#define APAD 20    // As row stride (floats): banks (20g+tig)%32 all distinct
#define BPAD 136   // Bs row stride (floats): banks (8tig+g)%32 all distinct

__global__ __launch_bounds__(256)
void gemm_tf32_kernel(const float* __restrict__ A, const float* __restrict__ W,
                      const float* __restrict__ bias, float* __restrict__ C,
                      int M, int Ntot, int K)
{
    __shared__ uint32_t As[BM * APAD];
    __shared__ uint32_t Bs[BKK * BPAD];

    const int tid  = threadIdx.x;
    const int lane = tid & 31;
    const int warp = tid >> 5;
    const int g    = lane >> 2;   // groupID
    const int tig  = lane & 3;    // threadID_in_group
    const int wm   = warp & 3;    // M offset wm*32
    const int wn   = warp >> 2;   // N offset wn*64
    const int bM   = blockIdx.y * BM;
    const int bN   = blockIdx.x * BN;

    float acc[2][8][4];
#pragma unroll
    for (int im = 0; im < 2; im++)
#pragma unroll
        for (int in_ = 0; in_ < 8; in_++)
#pragma unroll
            for (int j = 0; j < 4; j++) acc[im][in_][j] = 0.f;

    for (int k0 = 0; k0 < K; k0 += BKK) {
        // Load A tile: 128x16 = 512 float4
#pragma unroll
        for (int j = 0; j < 2; j++) {
            int idx = tid + j * 256;
            int r = idx >> 2;
            int c = (idx & 3) << 2;
            float4 v = *(const float4*)(A + (size_t)(bM + r) * K + k0 + c);
            uint32_t* dst = &As[r * APAD + c];
            dst[0] = f2tf32(v.x); dst[1] = f2tf32(v.y);
            dst[2] = f2tf32(v.z); dst[3] = f2tf32(v.w);
        }
        // Load B tile: 16x128 = 512 float4
#pragma unroll
        for (int j = 0; j < 2; j++) {
            int idx = tid + j * 256;
            int r = idx >> 5;
            int c = (idx & 31) << 2;
            float4 v = *(const float4*)(W + (size_t)(k0 + r) * Ntot + bN + c);
            uint32_t* dst = &Bs[r * BPAD + c];
            dst[0] = f2tf32(v.x); dst[1] = f2tf32(v.y);
            dst[2] = f2tf32(v.z); dst[3] = f2tf32(v.w);
        }
        __syncthreads();

#pragma unroll
        for (int kk = 0; kk < BKK; kk += 8) {
            uint32_t af[2][4];
#pragma unroll
            for (int im = 0; im < 2; im++) {
                int rb = wm * 32 + im * 16;
                af[im][0] = As[(rb + g)     * APAD + kk + tig];
                af[im][1] = As[(rb + g + 8) * APAD + kk + tig];
                af[im][2] = As[(rb + g)     * APAD + kk + tig + 4];
                af[im][3] = As[(rb + g + 8) * APAD + kk + tig + 4];
            }
            uint32_t bf[8][2];
#pragma unroll
            for (int in_ = 0; in_ < 8; in_++) {
                int cb = wn * 64 + in_ * 8 + g;
                bf[in_][0] = Bs[(kk + tig)     * BPAD + cb];
                bf[in_][1] = Bs[(kk + tig + 4) * BPAD + cb];
            }
#pragma unroll
            for (int im = 0; im < 2; im++)
#pragma unroll
                for (int in_ = 0; in_ < 8; in_++) {
                    float* d = acc[im][in_];
                    asm volatile(
                        "mma.sync.aligned.m16n8k8.row.col.f32.tf32.tf32.f32 "
                        "{%0,%1,%2,%3}, {%4,%5,%6,%7}, {%8,%9}, {%0,%1,%2,%3};\n"
                        : "+f"(d[0]), "+f"(d[1]), "+f"(d[2]), "+f"(d[3])
                        : "r"(af[im][0]), "r"(af[im][1]), "r"(af[im][2]), "r"(af[im][3]),
                          "r"(bf[in_][0]), "r"(bf[in_][1]));
                }
        }
        __syncthreads();
    }

    // Epilogue: bias + store (c0/c1 at cols 2*tig, 2*tig+1; c2/c3 at row+8)
#pragma unroll
    for (int im = 0; im < 2; im++) {
        int r0 = bM + wm * 32 + im * 16 + g;
#pragma unroll
        for (int in_ = 0; in_ < 8; in_++) {
            int c = bN + wn * 64 + in_ * 8 + 2 * tig;
            float b0 = bias[c], b1 = bias[c + 1];
            float2 v0 = make_float2(acc[im][in_][0] + b0, acc[im][in_][1] + b1);
            float2 v1 = make_float2(acc[im][in_][2] + b0, acc[im][in_][3] + b1);
            *(float2*)(C + (size_t)r0       * Ntot + c) = v0;
            *(float2*)(C + (size_t)(r0 + 8) * Ntot + c) = v1;
        }
    }
}

// ---------------------------------------------------------------------------
// Causal flash attention (fp32), Q/K/V/Y in [B, T, C] layout (head = 64-col slice)
// Block: 256 threads, 64 q-rows, 4 threads per row (each owns a 16-wide d-quarter)
// Grid: (32 q-tiles, 64 batch*head), heavy q-tiles scheduled first
// ---------------------------------------------------------------------------
__global__ __launch_bounds__(256)
void attn_kernel(const float* __restrict__ Q, const float* __restrict__ K,
                 const float* __restrict__ V, float* __restrict__ Y)
{
    __shared__ float Ks[64 * 64];
    __shared__ float Vs[64 * 64];

    const int tid  = threadIdx.x;
    const int lane = tid & 31;
    const int row  = tid >> 2;        // 0..63 : q row within tile
    const int q4   = tid & 3;         // 0..3  : d-quarter
    const int qt   = 31 - blockIdx.x; // heavy tiles first
    const int bh   = blockIdx.y;
    const int b    = bh >> 4;
    const int h    = bh & 15;
    const int qrow = qt * 64 + row;

    const size_t base = (size_t)b * SEQ * CDIM + (size_t)h * HDIM;

    // Load + pre-scale q row slice
    float qreg[16];
    {
        const float* qp = Q + base + (size_t)qrow * CDIM + q4 * 16;
        const float scale = 0.125f;   // 1/sqrt(64)
#pragma unroll
        for (int j = 0; j < 4; j++) {
            float4 v = *(const float4*)(qp + 4 * j);
            qreg[4 * j + 0] = v.x * scale;
            qreg[4 * j + 1] = v.y * scale;
            qreg[4 * j + 2] = v.z * scale;
            qreg[4 * j + 3] = v.w * scale;
        }
    }

    float O[16];
#pragma unroll
    for (int j = 0; j < 16; j++) O[j] = 0.f;
    float mrun = -1e30f, lrun = 0.f;

    for (int kt = 0; kt <= qt; kt++) {
        __syncthreads();
        // Load K and V tiles (64 rows x 64 cols)
#pragma unroll
        for (int j = 0; j < 4; j++) {
            int idx = tid + j * 256;         // 1024 float4 slots per tensor
            int r = idx >> 4;                // 16 float4 per row
            int c = (idx & 15) << 2;
            size_t goff = base + (size_t)(kt * 64 + r) * CDIM + c;
            *(float4*)&Ks[r * 64 + c] = *(const float4*)(K + goff);
            *(float4*)&Vs[r * 64 + c] = *(const float4*)(V + goff);
        }
        __syncthreads();

        // Scores for all 64 keys; each thread keeps the 16 it owns.
        // After the 4-lane shfl reduce, every lane in the group holds every
        // score, so the running tile-max needs no extra reduction.
        float tm = -1e30f;
        float sc[16];
        for (int s16 = 0; s16 < 4; s16++) {
#pragma unroll
            for (int si = 0; si < 16; si++) {
                int s = s16 * 16 + si;
                const float* kr = &Ks[s * 64 + q4 * 16];
                float p = 0.f;
#pragma unroll
                for (int j = 0; j < 4; j++) {
                    float4 kv = *(const float4*)(kr + 4 * j);
                    p += qreg[4 * j + 0] * kv.x + qreg[4 * j + 1] * kv.y
                       + qreg[4 * j + 2] * kv.z + qreg[4 * j + 3] * kv.w;
                }
                p += __shfl_xor_sync(0xffffffffu, p, 1);
                p += __shfl_xor_sync(0xffffffffu, p, 2);
                bool ok = (kt * 64 + s) <= qrow;
                float pm = ok ? p : -1e30f;
                tm = fmaxf(tm, pm);
                if (s16 == q4) sc[si] = pm;
            }
        }

        // Online softmax update
        float mnew  = fmaxf(mrun, tm);
        float alpha = __expf(mrun - mnew);
        lrun *= alpha;
#pragma unroll
        for (int j = 0; j < 16; j++) O[j] *= alpha;

        float pl[16];
        float ps = 0.f;
#pragma unroll
        for (int j = 0; j < 16; j++) {
            pl[j] = __expf(sc[j] - mnew);
            ps += pl[j];
        }
        ps += __shfl_xor_sync(0xffffffffu, ps, 1);
        ps += __shfl_xor_sync(0xffffffffu, ps, 2);
        lrun += ps;
        mrun = mnew;

        // O += P @ V  (p broadcast from the owning lane within the 4-lane group)
        for (int s16 = 0; s16 < 4; s16++) {
            int src = (lane & ~3) | s16;
#pragma unroll
            for (int si = 0; si < 16; si++) {
                float p = __shfl_sync(0xffffffffu, pl[si], src);
                const float* vr = &Vs[(s16 * 16 + si) * 64 + q4 * 16];
#pragma unroll
                for (int j = 0; j < 4; j++) {
                    float4 vv = *(const float4*)(vr + 4 * j);
                    O[4 * j + 0] += p * vv.x;
                    O[4 * j + 1] += p * vv.y;
                    O[4 * j + 2] += p * vv.z;
                    O[4 * j + 3] += p * vv.w;
                }
            }
        }
    }

    // Normalize and store
    float inv = 1.f / lrun;
    float* yp = Y + base + (size_t)qrow * CDIM + q4 * 16;
#pragma unroll
    for (int j = 0; j < 4; j++) {
        float4 v;
        v.x = O[4 * j + 0] * inv;
        v.y = O[4 * j + 1] * inv;
        v.z = O[4 * j + 2] * inv;
        v.w = O[4 * j + 3] * inv;
        *(float4*)(yp + 4 * j) = v;
    }
}

// ---------------------------------------------------------------------------
// Launch: 3 projection GEMMs -> attention -> output GEMM
// ---------------------------------------------------------------------------
extern "C" void kernel_launch(void* const* d_in, const int* in_sizes, int n_in,
                              void* d_out, int out_size)
{
    const float* x  = (const float*)d_in[0];
    const float* Wq = (const float*)d_in[1];
    const float* bq = (const float*)d_in[2];
    const float* Wk = (const float*)d_in[3];
    const float* bk = (const float*)d_in[4];
    const float* Wv = (const float*)d_in[5];
    const float* bv = (const float*)d_in[6];
    const float* Wp = (const float*)d_in[7];
    const float* bp = (const float*)d_in[8];
    float* out = (float*)d_out;

    float *Qb, *Kb, *Vb, *Yb;
    cudaGetSymbolAddress((void**)&Qb, g_Q);
    cudaGetSymbolAddress((void**)&Kb, g_K);
    cudaGetSymbolAddress((void**)&Vb, g_V);
    cudaGetSymbolAddress((void**)&Yb, g_Y);

    dim3 gGrid(CDIM / BN, MROWS / BM);   // (8, 64) = 512 blocks
    dim3 blk(256);

    gemm_tf32_kernel<<<gGrid, blk>>>(x,  Wq, bq, Qb, MROWS, CDIM, CDIM);
    gemm_tf32_kernel<<<gGrid, blk>>>(x,  Wk, bk, Kb, MROWS, CDIM, CDIM);
    gemm_tf32_kernel<<<gGrid, blk>>>(x,  Wv, bv, Vb, MROWS, CDIM, CDIM);

    dim3 aGrid(SEQ / 64, BATCH * N_HEADS);  // (32, 64)
    attn_kernel<<<aGrid, blk>>>(Qb, Kb, Vb, Yb);

    gemm_tf32_kernel<<<gGrid, blk>>>(Yb, Wp, bp, out, MROWS, CDIM, CDIM);
}

// round 2
// speedup vs baseline: 4.5661x; 4.5661x over previous
#include <cuda_runtime.h>
#include <cstdint>
#include <cstddef>

// Problem constants
#define N_HEADS 16
#define BATCH   4
#define SEQ     2048
#define CDIM    1024
#define HDIM    64
#define MROWS   (BATCH * SEQ)   // 8192

// ---------------------------------------------------------------------------
// Scratch (device globals: allocation-free rule)
// ---------------------------------------------------------------------------
__device__ float g_Q[(size_t)MROWS * CDIM];
__device__ float g_K[(size_t)MROWS * CDIM];
__device__ float g_V[(size_t)MROWS * CDIM];
__device__ float g_Y[(size_t)MROWS * CDIM];

// ---------------------------------------------------------------------------
// tf32 helper: round-to-nearest conversion (truncation would bias dot
// products low over K=1024 and fail the tolerance)
// ---------------------------------------------------------------------------
__device__ __forceinline__ uint32_t f2tf32(float x) {
    uint32_t r;
    asm("cvt.rna.tf32.f32 %0, %1;" : "=r"(r) : "f"(x));
    return r;
}

__device__ __forceinline__ void mma_tf32(float* d, uint32_t a0, uint32_t a1,
                                         uint32_t a2, uint32_t a3,
                                         uint32_t b0, uint32_t b1) {
    asm volatile(
        "mma.sync.aligned.m16n8k8.row.col.f32.tf32.tf32.f32 "
        "{%0,%1,%2,%3}, {%4,%5,%6,%7}, {%8,%9}, {%0,%1,%2,%3};\n"
        : "+f"(d[0]), "+f"(d[1]), "+f"(d[2]), "+f"(d[3])
        : "r"(a0), "r"(a1), "r"(a2), "r"(a3), "r"(b0), "r"(b1));
}

// ---------------------------------------------------------------------------
// GEMM: C[M,N] = A[M,K] @ W[K,N] + bias[N]   (fp32 gmem, tf32 MMA, fp32 accum)
// BM=128 BN=128 BK=16, 256 threads, warp grid 4(M) x 2(N), warp tile 32x64
// ---------------------------------------------------------------------------
#define BM 128
#define BN 128
#define BKK 16
#define APAD 20
#define BPAD 136

__global__ __launch_bounds__(256)
void gemm_tf32_kernel(const float* __restrict__ A, const float* __restrict__ W,
                      const float* __restrict__ bias, float* __restrict__ C,
                      int M, int Ntot, int K)
{
    __shared__ uint32_t As[BM * APAD];
    __shared__ uint32_t Bs[BKK * BPAD];

    const int tid  = threadIdx.x;
    const int lane = tid & 31;
    const int warp = tid >> 5;
    const int g    = lane >> 2;
    const int tig  = lane & 3;
    const int wm   = warp & 3;
    const int wn   = warp >> 2;
    const int bM   = blockIdx.y * BM;
    const int bN   = blockIdx.x * BN;

    float acc[2][8][4];
#pragma unroll
    for (int im = 0; im < 2; im++)
#pragma unroll
        for (int in_ = 0; in_ < 8; in_++)
#pragma unroll
            for (int j = 0; j < 4; j++) acc[im][in_][j] = 0.f;

    for (int k0 = 0; k0 < K; k0 += BKK) {
#pragma unroll
        for (int j = 0; j < 2; j++) {
            int idx = tid + j * 256;
            int r = idx >> 2;
            int c = (idx & 3) << 2;
            float4 v = *(const float4*)(A + (size_t)(bM + r) * K + k0 + c);
            uint32_t* dst = &As[r * APAD + c];
            dst[0] = f2tf32(v.x); dst[1] = f2tf32(v.y);
            dst[2] = f2tf32(v.z); dst[3] = f2tf32(v.w);
        }
#pragma unroll
        for (int j = 0; j < 2; j++) {
            int idx = tid + j * 256;
            int r = idx >> 5;
            int c = (idx & 31) << 2;
            float4 v = *(const float4*)(W + (size_t)(k0 + r) * Ntot + bN + c);
            uint32_t* dst = &Bs[r * BPAD + c];
            dst[0] = f2tf32(v.x); dst[1] = f2tf32(v.y);
            dst[2] = f2tf32(v.z); dst[3] = f2tf32(v.w);
        }
        __syncthreads();

#pragma unroll
        for (int kk = 0; kk < BKK; kk += 8) {
            uint32_t af[2][4];
#pragma unroll
            for (int im = 0; im < 2; im++) {
                int rb = wm * 32 + im * 16;
                af[im][0] = As[(rb + g)     * APAD + kk + tig];
                af[im][1] = As[(rb + g + 8) * APAD + kk + tig];
                af[im][2] = As[(rb + g)     * APAD + kk + tig + 4];
                af[im][3] = As[(rb + g + 8) * APAD + kk + tig + 4];
            }
            uint32_t bf[8][2];
#pragma unroll
            for (int in_ = 0; in_ < 8; in_++) {
                int cb = wn * 64 + in_ * 8 + g;
                bf[in_][0] = Bs[(kk + tig)     * BPAD + cb];
                bf[in_][1] = Bs[(kk + tig + 4) * BPAD + cb];
            }
#pragma unroll
            for (int im = 0; im < 2; im++)
#pragma unroll
                for (int in_ = 0; in_ < 8; in_++)
                    mma_tf32(acc[im][in_], af[im][0], af[im][1], af[im][2], af[im][3],
                             bf[in_][0], bf[in_][1]);
        }
        __syncthreads();
    }

#pragma unroll
    for (int im = 0; im < 2; im++) {
        int r0 = bM + wm * 32 + im * 16 + g;
#pragma unroll
        for (int in_ = 0; in_ < 8; in_++) {
            int c = bN + wn * 64 + in_ * 8 + 2 * tig;
            float b0 = bias[c], b1 = bias[c + 1];
            float2 v0 = make_float2(acc[im][in_][0] + b0, acc[im][in_][1] + b1);
            float2 v1 = make_float2(acc[im][in_][2] + b0, acc[im][in_][3] + b1);
            *(float2*)(C + (size_t)r0       * Ntot + c) = v0;
            *(float2*)(C + (size_t)(r0 + 8) * Ntot + c) = v1;
        }
    }
}

// ---------------------------------------------------------------------------
// Tensor-core causal flash attention (tf32 MMA, fp32 softmax/accum)
// Block: 128 threads (4 warps). 64 q-rows per block (16 per warp),
// 64-key tiles. Q/K/V/Y in [B, T, C] layout; head = 64-col slice.
// Smem rows padded to 68 u32 -> all fragment LDS patterns conflict-free
// ((4g+tig) mod 32 distinct), and uint4 stores stay 16B-aligned (272B pitch).
// ---------------------------------------------------------------------------
#define SPITCH 68

__global__ __launch_bounds__(128)
void attn_mma_kernel(const float* __restrict__ Q, const float* __restrict__ K,
                     const float* __restrict__ V, float* __restrict__ Y)
{
    __shared__ uint32_t Ks[64 * SPITCH];
    __shared__ uint32_t Vs[64 * SPITCH];
    __shared__ uint32_t Ps[64 * SPITCH];   // staging for Q, then per-warp P

    const int tid  = threadIdx.x;
    const int lane = tid & 31;
    const int warp = tid >> 5;       // 0..3
    const int g    = lane >> 2;      // 0..7  (row within fragment)
    const int tig  = lane & 3;       // 0..3
    const int rw   = warp * 16;      // warp's q-row base within tile

    const int qt = 31 - blockIdx.x;  // heavy tiles first
    const int bh = blockIdx.y;
    const int b  = bh >> 4;
    const int h  = bh & 15;
    const int qrow0 = qt * 64;

    const size_t base = (size_t)b * SEQ * CDIM + (size_t)h * HDIM;

    // ---- Stage Q tile into Ps (scaled, tf32), then extract A-fragments ----
    {
        const float scale = 0.125f;  // 1/sqrt(64)
#pragma unroll
        for (int j = 0; j < 8; j++) {
            int idx = tid + j * 128;        // 1024 float4 slots
            int r = idx >> 4;
            int c = (idx & 15) << 2;
            float4 v = *(const float4*)(Q + base + (size_t)(qrow0 + r) * CDIM + c);
            uint4 u;
            u.x = f2tf32(v.x * scale); u.y = f2tf32(v.y * scale);
            u.z = f2tf32(v.z * scale); u.w = f2tf32(v.w * scale);
            *(uint4*)&Ps[r * SPITCH + c] = u;
        }
    }
    __syncthreads();

    uint32_t qa[8][4];
#pragma unroll
    for (int kk = 0; kk < 8; kk++) {
        qa[kk][0] = Ps[(rw + g)     * SPITCH + kk * 8 + tig];
        qa[kk][1] = Ps[(rw + g + 8) * SPITCH + kk * 8 + tig];
        qa[kk][2] = Ps[(rw + g)     * SPITCH + kk * 8 + tig + 4];
        qa[kk][3] = Ps[(rw + g + 8) * SPITCH + kk * 8 + tig + 4];
    }

    float O[8][4];
#pragma unroll
    for (int nb = 0; nb < 8; nb++)
#pragma unroll
        for (int j = 0; j < 4; j++) O[nb][j] = 0.f;
    float m0 = -1e30f, m1 = -1e30f, l0 = 0.f, l1 = 0.f;

    for (int kt = 0; kt <= qt; kt++) {
        __syncthreads();
        // ---- Load K and V tiles as tf32 ----
#pragma unroll
        for (int j = 0; j < 8; j++) {
            int idx = tid + j * 128;
            int r = idx >> 4;
            int c = (idx & 15) << 2;
            size_t goff = base + (size_t)(kt * 64 + r) * CDIM + c;
            float4 kv = *(const float4*)(K + goff);
            float4 vv = *(const float4*)(V + goff);
            uint4 uk, uv;
            uk.x = f2tf32(kv.x); uk.y = f2tf32(kv.y);
            uk.z = f2tf32(kv.z); uk.w = f2tf32(kv.w);
            uv.x = f2tf32(vv.x); uv.y = f2tf32(vv.y);
            uv.z = f2tf32(vv.z); uv.w = f2tf32(vv.w);
            *(uint4*)&Ks[r * SPITCH + c] = uk;
            *(uint4*)&Vs[r * SPITCH + c] = uv;
        }
        __syncthreads();

        // ---- S = Q K^T : per warp 16x64, 8 n-tiles x 8 k-steps ----
        float s[8][4];
#pragma unroll
        for (int nb = 0; nb < 8; nb++) {
            s[nb][0] = s[nb][1] = s[nb][2] = s[nb][3] = 0.f;
#pragma unroll
            for (int kk = 0; kk < 8; kk++) {
                // B[k=d][n=key] = K[key][d]
                uint32_t b0 = Ks[(nb * 8 + g) * SPITCH + kk * 8 + tig];
                uint32_t b1 = Ks[(nb * 8 + g) * SPITCH + kk * 8 + tig + 4];
                mma_tf32(s[nb], qa[kk][0], qa[kk][1], qa[kk][2], qa[kk][3], b0, b1);
            }
        }

        // ---- Causal mask (only the diagonal tile needs it) ----
        if (kt == qt) {
#pragma unroll
            for (int nb = 0; nb < 8; nb++) {
                int kc = nb * 8 + 2 * tig;       // local key col
                int r0 = rw + g, r1 = rw + g + 8;
                if (kc     > r0) s[nb][0] = -1e30f;
                if (kc + 1 > r0) s[nb][1] = -1e30f;
                if (kc     > r1) s[nb][2] = -1e30f;
                if (kc + 1 > r1) s[nb][3] = -1e30f;
            }
        }

        // ---- Online softmax: rows g (c0,c1) and g+8 (c2,c3) ----
        float tm0 = -1e30f, tm1 = -1e30f;
#pragma unroll
        for (int nb = 0; nb < 8; nb++) {
            tm0 = fmaxf(tm0, fmaxf(s[nb][0], s[nb][1]));
            tm1 = fmaxf(tm1, fmaxf(s[nb][2], s[nb][3]));
        }
        tm0 = fmaxf(tm0, __shfl_xor_sync(0xffffffffu, tm0, 1));
        tm0 = fmaxf(tm0, __shfl_xor_sync(0xffffffffu, tm0, 2));
        tm1 = fmaxf(tm1, __shfl_xor_sync(0xffffffffu, tm1, 1));
        tm1 = fmaxf(tm1, __shfl_xor_sync(0xffffffffu, tm1, 2));

        float mn0 = fmaxf(m0, tm0), mn1 = fmaxf(m1, tm1);
        float a0 = __expf(m0 - mn0), a1 = __expf(m1 - mn1);
        l0 *= a0; l1 *= a1;
#pragma unroll
        for (int nb = 0; nb < 8; nb++) {
            O[nb][0] *= a0; O[nb][1] *= a0;
            O[nb][2] *= a1; O[nb][3] *= a1;
        }

        float rs0 = 0.f, rs1 = 0.f;
#pragma unroll
        for (int nb = 0; nb < 8; nb++) {
            float p0 = __expf(s[nb][0] - mn0);
            float p1 = __expf(s[nb][1] - mn0);
            float p2 = __expf(s[nb][2] - mn1);
            float p3 = __expf(s[nb][3] - mn1);
            rs0 += p0 + p1; rs1 += p2 + p3;
            // P to warp-private smem (C-frag -> A-frag layout conversion)
            uint2 u01 = make_uint2(f2tf32(p0), f2tf32(p1));
            uint2 u23 = make_uint2(f2tf32(p2), f2tf32(p3));
            *(uint2*)&Ps[(rw + g)     * SPITCH + nb * 8 + 2 * tig] = u01;
            *(uint2*)&Ps[(rw + g + 8) * SPITCH + nb * 8 + 2 * tig] = u23;
        }
        rs0 += __shfl_xor_sync(0xffffffffu, rs0, 1);
        rs0 += __shfl_xor_sync(0xffffffffu, rs0, 2);
        rs1 += __shfl_xor_sync(0xffffffffu, rs1, 1);
        rs1 += __shfl_xor_sync(0xffffffffu, rs1, 2);
        l0 += rs0; l1 += rs1;
        m0 = mn0; m1 = mn1;

        __syncwarp();

        // ---- O += P V : A = P (16x64) from smem, B = V (64x64) ----
#pragma unroll
        for (int kk = 0; kk < 8; kk++) {
            uint32_t pa0 = Ps[(rw + g)     * SPITCH + kk * 8 + tig];
            uint32_t pa1 = Ps[(rw + g + 8) * SPITCH + kk * 8 + tig];
            uint32_t pa2 = Ps[(rw + g)     * SPITCH + kk * 8 + tig + 4];
            uint32_t pa3 = Ps[(rw + g + 8) * SPITCH + kk * 8 + tig + 4];
#pragma unroll
            for (int nb = 0; nb < 8; nb++) {
                uint32_t b0 = Vs[(kk * 8 + tig)     * SPITCH + nb * 8 + g];
                uint32_t b1 = Vs[(kk * 8 + tig + 4) * SPITCH + nb * 8 + g];
                mma_tf32(O[nb], pa0, pa1, pa2, pa3, b0, b1);
            }
        }
        __syncwarp();   // protect Ps before next iteration's P stores
    }

    // ---- Epilogue: normalize and store ----
    float inv0 = 1.f / l0, inv1 = 1.f / l1;
    int r0 = qrow0 + rw + g;
    int r1 = r0 + 8;
#pragma unroll
    for (int nb = 0; nb < 8; nb++) {
        int c = nb * 8 + 2 * tig;  // d index within head
        float2 v0 = make_float2(O[nb][0] * inv0, O[nb][1] * inv0);
        float2 v1 = make_float2(O[nb][2] * inv1, O[nb][3] * inv1);
        *(float2*)(Y + base + (size_t)r0 * CDIM + c) = v0;
        *(float2*)(Y + base + (size_t)r1 * CDIM + c) = v1;
    }
}

// ---------------------------------------------------------------------------
// Launch: 3 projection GEMMs -> attention -> output GEMM
// ---------------------------------------------------------------------------
extern "C" void kernel_launch(void* const* d_in, const int* in_sizes, int n_in,
                              void* d_out, int out_size)
{
    const float* x  = (const float*)d_in[0];
    const float* Wq = (const float*)d_in[1];
    const float* bq = (const float*)d_in[2];
    const float* Wk = (const float*)d_in[3];
    const float* bk = (const float*)d_in[4];
    const float* Wv = (const float*)d_in[5];
    const float* bv = (const float*)d_in[6];
    const float* Wp = (const float*)d_in[7];
    const float* bp = (const float*)d_in[8];
    float* out = (float*)d_out;

    float *Qb, *Kb, *Vb, *Yb;
    cudaGetSymbolAddress((void**)&Qb, g_Q);
    cudaGetSymbolAddress((void**)&Kb, g_K);
    cudaGetSymbolAddress((void**)&Vb, g_V);
    cudaGetSymbolAddress((void**)&Yb, g_Y);

    dim3 gGrid(CDIM / BN, MROWS / BM);   // (8, 64) = 512 blocks
    dim3 gBlk(256);

    gemm_tf32_kernel<<<gGrid, gBlk>>>(x,  Wq, bq, Qb, MROWS, CDIM, CDIM);
    gemm_tf32_kernel<<<gGrid, gBlk>>>(x,  Wk, bk, Kb, MROWS, CDIM, CDIM);
    gemm_tf32_kernel<<<gGrid, gBlk>>>(x,  Wv, bv, Vb, MROWS, CDIM, CDIM);

    dim3 aGrid(SEQ / 64, BATCH * N_HEADS);  // (32, 64)
    attn_mma_kernel<<<aGrid, dim3(128)>>>(Qb, Kb, Vb, Yb);

    gemm_tf32_kernel<<<gGrid, gBlk>>>(Yb, Wp, bp, out, MROWS, CDIM, CDIM);
}

// round 3
// speedup vs baseline: 5.5158x; 1.2080x over previous
#include <cuda_runtime.h>
#include <cstdint>
#include <cstddef>

// Problem constants
#define N_HEADS 16
#define BATCH   4
#define SEQ     2048
#define CDIM    1024
#define HDIM    64
#define MROWS   (BATCH * SEQ)   // 8192

// ---------------------------------------------------------------------------
// Scratch (device globals: allocation-free rule)
// ---------------------------------------------------------------------------
__device__ float g_Q[(size_t)MROWS * CDIM];
__device__ float g_K[(size_t)MROWS * CDIM];
__device__ float g_V[(size_t)MROWS * CDIM];
__device__ float g_Y[(size_t)MROWS * CDIM];

// ---------------------------------------------------------------------------
// tf32 helper: round-to-nearest conversion (truncation would bias dot
// products low over K=1024 and fail the tolerance)
// ---------------------------------------------------------------------------
__device__ __forceinline__ uint32_t f2tf32(float x) {
    uint32_t r;
    asm("cvt.rna.tf32.f32 %0, %1;" : "=r"(r) : "f"(x));
    return r;
}

__device__ __forceinline__ void mma_tf32(float* d, uint32_t a0, uint32_t a1,
                                         uint32_t a2, uint32_t a3,
                                         uint32_t b0, uint32_t b1) {
    asm volatile(
        "mma.sync.aligned.m16n8k8.row.col.f32.tf32.tf32.f32 "
        "{%0,%1,%2,%3}, {%4,%5,%6,%7}, {%8,%9}, {%0,%1,%2,%3};\n"
        : "+f"(d[0]), "+f"(d[1]), "+f"(d[2]), "+f"(d[3])
        : "r"(a0), "r"(a1), "r"(a2), "r"(a3), "r"(b0), "r"(b1));
}

// ---------------------------------------------------------------------------
// Pipelined GEMM: C[M,N] = A[M,K] @ W[K,N] + bias[N]
// BM=128 BN=128 BK=16, 256 threads, double-buffered smem with register
// prefetch: LDG(t+1) -> MMA(t) -> STS(t+1) -> one sync per tile.
// blockIdx.z selects among up to 3 (W, bias, C) triples (fused QKV).
// ---------------------------------------------------------------------------
#define BM 128
#define BN 128
#define BKK 16
#define APAD 20
#define BPAD 136

__global__ __launch_bounds__(256, 2)
void gemm_tf32_pipe(const float* __restrict__ A,
                    const float* __restrict__ Wa, const float* __restrict__ ba,
                    float* __restrict__ Ca,
                    const float* __restrict__ Wb, const float* __restrict__ bb,
                    float* __restrict__ Cb,
                    const float* __restrict__ Wc, const float* __restrict__ bc,
                    float* __restrict__ Cc,
                    int M, int Ntot, int K)
{
    const int z = blockIdx.z;
    const float* W    = (z == 0) ? Wa : (z == 1) ? Wb : Wc;
    const float* bias = (z == 0) ? ba : (z == 1) ? bb : bc;
    float*       C    = (z == 0) ? Ca : (z == 1) ? Cb : Cc;

    __shared__ uint32_t As[2][BM * APAD];
    __shared__ uint32_t Bs[2][BKK * BPAD];

    const int tid  = threadIdx.x;
    const int lane = tid & 31;
    const int warp = tid >> 5;
    const int g    = lane >> 2;
    const int tig  = lane & 3;
    const int wm   = warp & 3;
    const int wn   = warp >> 2;
    const int bM   = blockIdx.y * BM;
    const int bN   = blockIdx.x * BN;

    // Per-thread load coordinates (2 float4 for A, 2 for B per tile)
    const int idxA0 = tid,        idxA1 = tid + 256;
    const int rA0 = idxA0 >> 2,   cA0 = (idxA0 & 3) << 2;
    const int rA1 = idxA1 >> 2,   cA1 = (idxA1 & 3) << 2;
    const int rB0 = idxA0 >> 5,   cB0 = (idxA0 & 31) << 2;
    const int rB1 = idxA1 >> 5,   cB1 = (idxA1 & 31) << 2;

    const float* pA0 = A + (size_t)(bM + rA0) * K + cA0;
    const float* pA1 = A + (size_t)(bM + rA1) * K + cA1;
    const float* pB0 = W + (size_t)rB0 * Ntot + bN + cB0;
    const float* pB1 = W + (size_t)rB1 * Ntot + bN + cB1;

    const int sA0 = rA0 * APAD + cA0;
    const int sA1 = rA1 * APAD + cA1;
    const int sB0 = rB0 * BPAD + cB0;
    const int sB1 = rB1 * BPAD + cB1;

    float acc[2][8][4];
#pragma unroll
    for (int im = 0; im < 2; im++)
#pragma unroll
        for (int in_ = 0; in_ < 8; in_++)
#pragma unroll
            for (int j = 0; j < 4; j++) acc[im][in_][j] = 0.f;

    // Prologue: tile 0 -> buffer 0
    {
        float4 a0 = *(const float4*)pA0;
        float4 a1 = *(const float4*)pA1;
        float4 b0 = *(const float4*)pB0;
        float4 b1 = *(const float4*)pB1;
        uint32_t* d;
        d = &As[0][sA0]; d[0]=f2tf32(a0.x); d[1]=f2tf32(a0.y); d[2]=f2tf32(a0.z); d[3]=f2tf32(a0.w);
        d = &As[0][sA1]; d[0]=f2tf32(a1.x); d[1]=f2tf32(a1.y); d[2]=f2tf32(a1.z); d[3]=f2tf32(a1.w);
        d = &Bs[0][sB0]; d[0]=f2tf32(b0.x); d[1]=f2tf32(b0.y); d[2]=f2tf32(b0.z); d[3]=f2tf32(b0.w);
        d = &Bs[0][sB1]; d[0]=f2tf32(b1.x); d[1]=f2tf32(b1.y); d[2]=f2tf32(b1.z); d[3]=f2tf32(b1.w);
    }
    __syncthreads();

    const int nTiles = K / BKK;
    for (int t = 0; t < nTiles; t++) {
        const int buf = t & 1;
        const bool has = (t + 1) < nTiles;

        // Prefetch next tile into registers (hidden behind the MMAs below)
        float4 a0, a1, b0, b1;
        if (has) {
            const int ko = (t + 1) * BKK;
            a0 = *(const float4*)(pA0 + ko);
            a1 = *(const float4*)(pA1 + ko);
            b0 = *(const float4*)(pB0 + (size_t)ko * Ntot);
            b1 = *(const float4*)(pB1 + (size_t)ko * Ntot);
        }

        // Compute on current buffer
#pragma unroll
        for (int kk = 0; kk < BKK; kk += 8) {
            uint32_t af[2][4];
#pragma unroll
            for (int im = 0; im < 2; im++) {
                int rb = wm * 32 + im * 16;
                af[im][0] = As[buf][(rb + g)     * APAD + kk + tig];
                af[im][1] = As[buf][(rb + g + 8) * APAD + kk + tig];
                af[im][2] = As[buf][(rb + g)     * APAD + kk + tig + 4];
                af[im][3] = As[buf][(rb + g + 8) * APAD + kk + tig + 4];
            }
            uint32_t bf[8][2];
#pragma unroll
            for (int in_ = 0; in_ < 8; in_++) {
                int cb = wn * 64 + in_ * 8 + g;
                bf[in_][0] = Bs[buf][(kk + tig)     * BPAD + cb];
                bf[in_][1] = Bs[buf][(kk + tig + 4) * BPAD + cb];
            }
#pragma unroll
            for (int im = 0; im < 2; im++)
#pragma unroll
                for (int in_ = 0; in_ < 8; in_++)
                    mma_tf32(acc[im][in_], af[im][0], af[im][1], af[im][2], af[im][3],
                             bf[in_][0], bf[in_][1]);
        }

        if (has) {
            const int nb = buf ^ 1;
            uint32_t* d;
            d = &As[nb][sA0]; d[0]=f2tf32(a0.x); d[1]=f2tf32(a0.y); d[2]=f2tf32(a0.z); d[3]=f2tf32(a0.w);
            d = &As[nb][sA1]; d[0]=f2tf32(a1.x); d[1]=f2tf32(a1.y); d[2]=f2tf32(a1.z); d[3]=f2tf32(a1.w);
            d = &Bs[nb][sB0]; d[0]=f2tf32(b0.x); d[1]=f2tf32(b0.y); d[2]=f2tf32(b0.z); d[3]=f2tf32(b0.w);
            d = &Bs[nb][sB1]; d[0]=f2tf32(b1.x); d[1]=f2tf32(b1.y); d[2]=f2tf32(b1.z); d[3]=f2tf32(b1.w);
            __syncthreads();
        }
    }

    // Epilogue: bias + store
#pragma unroll
    for (int im = 0; im < 2; im++) {
        int r0 = bM + wm * 32 + im * 16 + g;
#pragma unroll
        for (int in_ = 0; in_ < 8; in_++) {
            int c = bN + wn * 64 + in_ * 8 + 2 * tig;
            float bv0 = bias[c], bv1 = bias[c + 1];
            float2 v0 = make_float2(acc[im][in_][0] + bv0, acc[im][in_][1] + bv1);
            float2 v1 = make_float2(acc[im][in_][2] + bv0, acc[im][in_][3] + bv1);
            *(float2*)(C + (size_t)r0       * Ntot + c) = v0;
            *(float2*)(C + (size_t)(r0 + 8) * Ntot + c) = v1;
        }
    }
}

// ---------------------------------------------------------------------------
// Tensor-core causal flash attention (tf32 MMA, fp32 softmax/accum)
// Block: 128 threads (4 warps). 64 q-rows per block, 64-key tiles.
// __launch_bounds__(128,3): cap regs so 3 blocks/SM fit (was 2.8 @ 168 regs).
// ---------------------------------------------------------------------------
#define SPITCH 68

__global__ __launch_bounds__(128, 3)
void attn_mma_kernel(const float* __restrict__ Q, const float* __restrict__ K,
                     const float* __restrict__ V, float* __restrict__ Y)
{
    __shared__ uint32_t Ks[64 * SPITCH];
    __shared__ uint32_t Vs[64 * SPITCH];
    __shared__ uint32_t Ps[64 * SPITCH];   // staging for Q, then per-warp P

    const int tid  = threadIdx.x;
    const int lane = tid & 31;
    const int warp = tid >> 5;
    const int g    = lane >> 2;
    const int tig  = lane & 3;
    const int rw   = warp * 16;

    const int qt = 31 - blockIdx.x;  // heavy tiles first
    const int bh = blockIdx.y;
    const int b  = bh >> 4;
    const int h  = bh & 15;
    const int qrow0 = qt * 64;

    const size_t base = (size_t)b * SEQ * CDIM + (size_t)h * HDIM;

    // ---- Stage Q tile into Ps (scaled, tf32), then extract A-fragments ----
    {
        const float scale = 0.125f;  // 1/sqrt(64)
#pragma unroll
        for (int j = 0; j < 8; j++) {
            int idx = tid + j * 128;
            int r = idx >> 4;
            int c = (idx & 15) << 2;
            float4 v = *(const float4*)(Q + base + (size_t)(qrow0 + r) * CDIM + c);
            uint4 u;
            u.x = f2tf32(v.x * scale); u.y = f2tf32(v.y * scale);
            u.z = f2tf32(v.z * scale); u.w = f2tf32(v.w * scale);
            *(uint4*)&Ps[r * SPITCH + c] = u;
        }
    }
    __syncthreads();

    uint32_t qa[8][4];
#pragma unroll
    for (int kk = 0; kk < 8; kk++) {
        qa[kk][0] = Ps[(rw + g)     * SPITCH + kk * 8 + tig];
        qa[kk][1] = Ps[(rw + g + 8) * SPITCH + kk * 8 + tig];
        qa[kk][2] = Ps[(rw + g)     * SPITCH + kk * 8 + tig + 4];
        qa[kk][3] = Ps[(rw + g + 8) * SPITCH + kk * 8 + tig + 4];
    }

    float O[8][4];
#pragma unroll
    for (int nb = 0; nb < 8; nb++)
#pragma unroll
        for (int j = 0; j < 4; j++) O[nb][j] = 0.f;
    float m0 = -1e30f, m1 = -1e30f, l0 = 0.f, l1 = 0.f;

    for (int kt = 0; kt <= qt; kt++) {
        __syncthreads();
#pragma unroll
        for (int j = 0; j < 8; j++) {
            int idx = tid + j * 128;
            int r = idx >> 4;
            int c = (idx & 15) << 2;
            size_t goff = base + (size_t)(kt * 64 + r) * CDIM + c;
            float4 kv = *(const float4*)(K + goff);
            float4 vv = *(const float4*)(V + goff);
            uint4 uk, uv;
            uk.x = f2tf32(kv.x); uk.y = f2tf32(kv.y);
            uk.z = f2tf32(kv.z); uk.w = f2tf32(kv.w);
            uv.x = f2tf32(vv.x); uv.y = f2tf32(vv.y);
            uv.z = f2tf32(vv.z); uv.w = f2tf32(vv.w);
            *(uint4*)&Ks[r * SPITCH + c] = uk;
            *(uint4*)&Vs[r * SPITCH + c] = uv;
        }
        __syncthreads();

        // ---- S = Q K^T ----
        float s[8][4];
#pragma unroll
        for (int nb = 0; nb < 8; nb++) {
            s[nb][0] = s[nb][1] = s[nb][2] = s[nb][3] = 0.f;
#pragma unroll
            for (int kk = 0; kk < 8; kk++) {
                uint32_t b0 = Ks[(nb * 8 + g) * SPITCH + kk * 8 + tig];
                uint32_t b1 = Ks[(nb * 8 + g) * SPITCH + kk * 8 + tig + 4];
                mma_tf32(s[nb], qa[kk][0], qa[kk][1], qa[kk][2], qa[kk][3], b0, b1);
            }
        }

        // ---- Causal mask (diagonal tile only) ----
        if (kt == qt) {
#pragma unroll
            for (int nb = 0; nb < 8; nb++) {
                int kc = nb * 8 + 2 * tig;
                int r0 = rw + g, r1 = rw + g + 8;
                if (kc     > r0) s[nb][0] = -1e30f;
                if (kc + 1 > r0) s[nb][1] = -1e30f;
                if (kc     > r1) s[nb][2] = -1e30f;
                if (kc + 1 > r1) s[nb][3] = -1e30f;
            }
        }

        // ---- Online softmax ----
        float tm0 = -1e30f, tm1 = -1e30f;
#pragma unroll
        for (int nb = 0; nb < 8; nb++) {
            tm0 = fmaxf(tm0, fmaxf(s[nb][0], s[nb][1]));
            tm1 = fmaxf(tm1, fmaxf(s[nb][2], s[nb][3]));
        }
        tm0 = fmaxf(tm0, __shfl_xor_sync(0xffffffffu, tm0, 1));
        tm0 = fmaxf(tm0, __shfl_xor_sync(0xffffffffu, tm0, 2));
        tm1 = fmaxf(tm1, __shfl_xor_sync(0xffffffffu, tm1, 1));
        tm1 = fmaxf(tm1, __shfl_xor_sync(0xffffffffu, tm1, 2));

        float mn0 = fmaxf(m0, tm0), mn1 = fmaxf(m1, tm1);
        float a0 = __expf(m0 - mn0), a1 = __expf(m1 - mn1);
        l0 *= a0; l1 *= a1;
#pragma unroll
        for (int nb = 0; nb < 8; nb++) {
            O[nb][0] *= a0; O[nb][1] *= a0;
            O[nb][2] *= a1; O[nb][3] *= a1;
        }

        float rs0 = 0.f, rs1 = 0.f;
#pragma unroll
        for (int nb = 0; nb < 8; nb++) {
            float p0 = __expf(s[nb][0] - mn0);
            float p1 = __expf(s[nb][1] - mn0);
            float p2 = __expf(s[nb][2] - mn1);
            float p3 = __expf(s[nb][3] - mn1);
            rs0 += p0 + p1; rs1 += p2 + p3;
            uint2 u01 = make_uint2(f2tf32(p0), f2tf32(p1));
            uint2 u23 = make_uint2(f2tf32(p2), f2tf32(p3));
            *(uint2*)&Ps[(rw + g)     * SPITCH + nb * 8 + 2 * tig] = u01;
            *(uint2*)&Ps[(rw + g + 8) * SPITCH + nb * 8 + 2 * tig] = u23;
        }
        rs0 += __shfl_xor_sync(0xffffffffu, rs0, 1);
        rs0 += __shfl_xor_sync(0xffffffffu, rs0, 2);
        rs1 += __shfl_xor_sync(0xffffffffu, rs1, 1);
        rs1 += __shfl_xor_sync(0xffffffffu, rs1, 2);
        l0 += rs0; l1 += rs1;
        m0 = mn0; m1 = mn1;

        __syncwarp();

        // ---- O += P V ----
#pragma unroll
        for (int kk = 0; kk < 8; kk++) {
            uint32_t pa0 = Ps[(rw + g)     * SPITCH + kk * 8 + tig];
            uint32_t pa1 = Ps[(rw + g + 8) * SPITCH + kk * 8 + tig];
            uint32_t pa2 = Ps[(rw + g)     * SPITCH + kk * 8 + tig + 4];
            uint32_t pa3 = Ps[(rw + g + 8) * SPITCH + kk * 8 + tig + 4];
#pragma unroll
            for (int nb = 0; nb < 8; nb++) {
                uint32_t b0 = Vs[(kk * 8 + tig)     * SPITCH + nb * 8 + g];
                uint32_t b1 = Vs[(kk * 8 + tig + 4) * SPITCH + nb * 8 + g];
                mma_tf32(O[nb], pa0, pa1, pa2, pa3, b0, b1);
            }
        }
        __syncwarp();
    }

    // ---- Epilogue ----
    float inv0 = 1.f / l0, inv1 = 1.f / l1;
    int r0 = qrow0 + rw + g;
    int r1 = r0 + 8;
#pragma unroll
    for (int nb = 0; nb < 8; nb++) {
        int c = nb * 8 + 2 * tig;
        float2 v0 = make_float2(O[nb][0] * inv0, O[nb][1] * inv0);
        float2 v1 = make_float2(O[nb][2] * inv1, O[nb][3] * inv1);
        *(float2*)(Y + base + (size_t)r0 * CDIM + c) = v0;
        *(float2*)(Y + base + (size_t)r1 * CDIM + c) = v1;
    }
}

// ---------------------------------------------------------------------------
// Launch: fused QKV GEMM -> attention -> output GEMM
// ---------------------------------------------------------------------------
extern "C" void kernel_launch(void* const* d_in, const int* in_sizes, int n_in,
                              void* d_out, int out_size)
{
    const float* x  = (const float*)d_in[0];
    const float* Wq = (const float*)d_in[1];
    const float* bq = (const float*)d_in[2];
    const float* Wk = (const float*)d_in[3];
    const float* bk = (const float*)d_in[4];
    const float* Wv = (const float*)d_in[5];
    const float* bv = (const float*)d_in[6];
    const float* Wp = (const float*)d_in[7];
    const float* bp = (const float*)d_in[8];
    float* out = (float*)d_out;

    float *Qb, *Kb, *Vb, *Yb;
    cudaGetSymbolAddress((void**)&Qb, g_Q);
    cudaGetSymbolAddress((void**)&Kb, g_K);
    cudaGetSymbolAddress((void**)&Vb, g_V);
    cudaGetSymbolAddress((void**)&Yb, g_Y);

    dim3 blk(256);

    // Fused Q/K/V projections: grid.z picks the weight/output triple
    dim3 qkvGrid(CDIM / BN, MROWS / BM, 3);   // (8, 64, 3)
    gemm_tf32_pipe<<<qkvGrid, blk>>>(x,
                                     Wq, bq, Qb,
                                     Wk, bk, Kb,
                                     Wv, bv, Vb,
                                     MROWS, CDIM, CDIM);

    dim3 aGrid(SEQ / 64, BATCH * N_HEADS);    // (32, 64)
    attn_mma_kernel<<<aGrid, dim3(128)>>>(Qb, Kb, Vb, Yb);

    // Output projection
    dim3 pGrid(CDIM / BN, MROWS / BM, 1);
    gemm_tf32_pipe<<<pGrid, blk>>>(Yb,
                                   Wp, bp, out,
                                   Wp, bp, out,
                                   Wp, bp, out,
                                   MROWS, CDIM, CDIM);
}

// round 6
// speedup vs baseline: 6.0330x; 1.0938x over previous
#include <cuda_runtime.h>
#include <cstdint>
#include <cstddef>

// Problem constants
#define N_HEADS 16
#define BATCH   4
#define SEQ     2048
#define CDIM    1024
#define HDIM    64
#define MROWS   (BATCH * SEQ)   // 8192

// ---------------------------------------------------------------------------
// Scratch (device globals: allocation-free rule)
// ---------------------------------------------------------------------------
__device__ float g_Q[(size_t)MROWS * CDIM];
__device__ float g_K[(size_t)MROWS * CDIM];
__device__ float g_V[(size_t)MROWS * CDIM];
__device__ float g_Y[(size_t)MROWS * CDIM];

// ---------------------------------------------------------------------------
// tf32 helper: round-to-nearest conversion (truncation would bias dot
// products low over K=1024 and fail the tolerance)
// ---------------------------------------------------------------------------
__device__ __forceinline__ uint32_t f2tf32(float x) {
    uint32_t r;
    asm("cvt.rna.tf32.f32 %0, %1;" : "=r"(r) : "f"(x));
    return r;
}

__device__ __forceinline__ void mma_tf32(float* d, uint32_t a0, uint32_t a1,
                                         uint32_t a2, uint32_t a3,
                                         uint32_t b0, uint32_t b1) {
    asm volatile(
        "mma.sync.aligned.m16n8k8.row.col.f32.tf32.tf32.f32 "
        "{%0,%1,%2,%3}, {%4,%5,%6,%7}, {%8,%9}, {%0,%1,%2,%3};\n"
        : "+f"(d[0]), "+f"(d[1]), "+f"(d[2]), "+f"(d[3])
        : "r"(a0), "r"(a1), "r"(a2), "r"(a3), "r"(b0), "r"(b1));
}

// ---------------------------------------------------------------------------
// Pipelined GEMM: C[M,N] = A[M,K] @ W[K,N] + bias[N]
// BM=128 BN=128 BK=16. 128 threads = 4 warps, each owning a 64x64 C-tile
// (2x2 warp grid): fragment LDS traffic is 4B/MMA vs 6B/MMA at 32x64.
// Double-buffered smem, register prefetch: LDG(t+1) -> MMA(t) -> STS(t+1)
// -> one sync per tile. blockIdx.z selects among 3 (W, bias, C) triples.
// ---------------------------------------------------------------------------
#define BM 128
#define BN 128
#define BKK 16
#define APAD 20    // A row stride (u32): banks (20g+tig)%32 all distinct
#define BPAD 136   // B row stride (u32): banks (8tig+g)%32 all distinct

__global__ __launch_bounds__(128, 2)
void gemm_tf32_pipe(const float* __restrict__ A,
                    const float* __restrict__ Wa, const float* __restrict__ ba,
                    float* __restrict__ Ca,
                    const float* __restrict__ Wb, const float* __restrict__ bb,
                    float* __restrict__ Cb,
                    const float* __restrict__ Wc, const float* __restrict__ bc,
                    float* __restrict__ Cc,
                    int M, int Ntot, int K)
{
    const int z = blockIdx.z;
    const float* W    = (z == 0) ? Wa : (z == 1) ? Wb : Wc;
    const float* bias = (z == 0) ? ba : (z == 1) ? bb : bc;
    float*       C    = (z == 0) ? Ca : (z == 1) ? Cb : Cc;

    __shared__ uint32_t As[2][BM * APAD];
    __shared__ uint32_t Bs[2][BKK * BPAD];

    const int tid  = threadIdx.x;
    const int lane = tid & 31;
    const int warp = tid >> 5;     // 0..3
    const int g    = lane >> 2;
    const int tig  = lane & 3;
    const int wm   = warp & 1;     // M half: rows wm*64
    const int wn   = warp >> 1;    // N half: cols wn*64
    const int bM   = blockIdx.y * BM;
    const int bN   = blockIdx.x * BN;

    // Per-thread load coordinates: 4 float4 for A, 4 for B per K16 tile
    const float* pA[4]; const float* pB[4];
    int sA[4], sB[4];
#pragma unroll
    for (int j = 0; j < 4; j++) {
        int idx = tid + j * 128;          // 0..511
        int rA = idx >> 2,  cA = (idx & 3) << 2;
        int rB = idx >> 5,  cB = (idx & 31) << 2;
        pA[j] = A + (size_t)(bM + rA) * K + cA;
        pB[j] = W + (size_t)rB * Ntot + bN + cB;
        sA[j] = rA * APAD + cA;
        sB[j] = rB * BPAD + cB;
    }

    float acc[4][8][4];
#pragma unroll
    for (int im = 0; im < 4; im++)
#pragma unroll
        for (int nb = 0; nb < 8; nb++)
#pragma unroll
            for (int j = 0; j < 4; j++) acc[im][nb][j] = 0.f;

    // Prologue: tile 0 -> buffer 0
#pragma unroll
    for (int j = 0; j < 4; j++) {
        float4 a = *(const float4*)pA[j];
        float4 b = *(const float4*)pB[j];
        uint32_t* d;
        d = &As[0][sA[j]]; d[0]=f2tf32(a.x); d[1]=f2tf32(a.y); d[2]=f2tf32(a.z); d[3]=f2tf32(a.w);
        d = &Bs[0][sB[j]]; d[0]=f2tf32(b.x); d[1]=f2tf32(b.y); d[2]=f2tf32(b.z); d[3]=f2tf32(b.w);
    }
    __syncthreads();

    const int nTiles = K / BKK;
    for (int t = 0; t < nTiles; t++) {
        const int buf = t & 1;
        const bool has = (t + 1) < nTiles;

        // Prefetch next tile into registers (hidden behind the MMAs below)
        float4 fa[4], fb[4];
        if (has) {
            const int ko = (t + 1) * BKK;
#pragma unroll
            for (int j = 0; j < 4; j++) {
                fa[j] = *(const float4*)(pA[j] + ko);
                fb[j] = *(const float4*)(pB[j] + (size_t)ko * Ntot);
            }
        }

        // Compute on current buffer: 2 K8 steps x (4 im x 8 nb) MMAs
#pragma unroll
        for (int kk = 0; kk < BKK; kk += 8) {
            uint32_t af[4][4];
#pragma unroll
            for (int im = 0; im < 4; im++) {
                int rb = wm * 64 + im * 16;
                af[im][0] = As[buf][(rb + g)     * APAD + kk + tig];
                af[im][1] = As[buf][(rb + g + 8) * APAD + kk + tig];
                af[im][2] = As[buf][(rb + g)     * APAD + kk + tig + 4];
                af[im][3] = As[buf][(rb + g + 8) * APAD + kk + tig + 4];
            }
            uint32_t bf[8][2];
#pragma unroll
            for (int nb = 0; nb < 8; nb++) {
                int cb = wn * 64 + nb * 8 + g;
                bf[nb][0] = Bs[buf][(kk + tig)     * BPAD + cb];
                bf[nb][1] = Bs[buf][(kk + tig + 4) * BPAD + cb];
            }
#pragma unroll
            for (int im = 0; im < 4; im++)
#pragma unroll
                for (int nb = 0; nb < 8; nb++)
                    mma_tf32(acc[im][nb], af[im][0], af[im][1], af[im][2], af[im][3],
                             bf[nb][0], bf[nb][1]);
        }

        if (has) {
            const int nxt = buf ^ 1;
#pragma unroll
            for (int j = 0; j < 4; j++) {
                uint32_t* d;
                d = &As[nxt][sA[j]]; d[0]=f2tf32(fa[j].x); d[1]=f2tf32(fa[j].y); d[2]=f2tf32(fa[j].z); d[3]=f2tf32(fa[j].w);
                d = &Bs[nxt][sB[j]]; d[0]=f2tf32(fb[j].x); d[1]=f2tf32(fb[j].y); d[2]=f2tf32(fb[j].z); d[3]=f2tf32(fb[j].w);
            }
            __syncthreads();
        }
    }

    // Epilogue: bias + store
#pragma unroll
    for (int im = 0; im < 4; im++) {
        int r0 = bM + wm * 64 + im * 16 + g;
#pragma unroll
        for (int nb = 0; nb < 8; nb++) {
            int c = bN + wn * 64 + nb * 8 + 2 * tig;
            float bv0 = bias[c], bv1 = bias[c + 1];
            float2 v0 = make_float2(acc[im][nb][0] + bv0, acc[im][nb][1] + bv1);
            float2 v1 = make_float2(acc[im][nb][2] + bv0, acc[im][nb][3] + bv1);
            *(float2*)(C + (size_t)r0       * Ntot + c) = v0;
            *(float2*)(C + (size_t)(r0 + 8) * Ntot + c) = v1;
        }
    }
}

// ---------------------------------------------------------------------------
// Tensor-core causal flash attention (tf32 MMA, fp32 softmax/accum)
// Block: 128 threads (4 warps). 64 q-rows per block, 64-key tiles.
// ---------------------------------------------------------------------------
#define SPITCH 68

__global__ __launch_bounds__(128, 3)
void attn_mma_kernel(const float* __restrict__ Q, const float* __restrict__ K,
                     const float* __restrict__ V, float* __restrict__ Y)
{
    __shared__ uint32_t Ks[64 * SPITCH];
    __shared__ uint32_t Vs[64 * SPITCH];
    __shared__ uint32_t Ps[64 * SPITCH];

    const int tid  = threadIdx.x;
    const int lane = tid & 31;
    const int warp = tid >> 5;
    const int g    = lane >> 2;
    const int tig  = lane & 3;
    const int rw   = warp * 16;

    const int qt = 31 - blockIdx.x;  // heavy tiles first
    const int bh = blockIdx.y;
    const int b  = bh >> 4;
    const int h  = bh & 15;
    const int qrow0 = qt * 64;

    const size_t base = (size_t)b * SEQ * CDIM + (size_t)h * HDIM;

    {
        const float scale = 0.125f;  // 1/sqrt(64)
#pragma unroll
        for (int j = 0; j < 8; j++) {
            int idx = tid + j * 128;
            int r = idx >> 4;
            int c = (idx & 15) << 2;
            float4 v = *(const float4*)(Q + base + (size_t)(qrow0 + r) * CDIM + c);
            uint4 u;
            u.x = f2tf32(v.x * scale); u.y = f2tf32(v.y * scale);
            u.z = f2tf32(v.z * scale); u.w = f2tf32(v.w * scale);
            *(uint4*)&Ps[r * SPITCH + c] = u;
        }
    }
    __syncthreads();

    uint32_t qa[8][4];
#pragma unroll
    for (int kk = 0; kk < 8; kk++) {
        qa[kk][0] = Ps[(rw + g)     * SPITCH + kk * 8 + tig];
        qa[kk][1] = Ps[(rw + g + 8) * SPITCH + kk * 8 + tig];
        qa[kk][2] = Ps[(rw + g)     * SPITCH + kk * 8 + tig + 4];
        qa[kk][3] = Ps[(rw + g + 8) * SPITCH + kk * 8 + tig + 4];
    }

    float O[8][4];
#pragma unroll
    for (int nb = 0; nb < 8; nb++)
#pragma unroll
        for (int j = 0; j < 4; j++) O[nb][j] = 0.f;
    float m0 = -1e30f, m1 = -1e30f, l0 = 0.f, l1 = 0.f;

    for (int kt = 0; kt <= qt; kt++) {
        __syncthreads();
#pragma unroll
        for (int j = 0; j < 8; j++) {
            int idx = tid + j * 128;
            int r = idx >> 4;
            int c = (idx & 15) << 2;
            size_t goff = base + (size_t)(kt * 64 + r) * CDIM + c;
            float4 kv = *(const float4*)(K + goff);
            float4 vv = *(const float4*)(V + goff);
            uint4 uk, uv;
            uk.x = f2tf32(kv.x); uk.y = f2tf32(kv.y);
            uk.z = f2tf32(kv.z); uk.w = f2tf32(kv.w);
            uv.x = f2tf32(vv.x); uv.y = f2tf32(vv.y);
            uv.z = f2tf32(vv.z); uv.w = f2tf32(vv.w);
            *(uint4*)&Ks[r * SPITCH + c] = uk;
            *(uint4*)&Vs[r * SPITCH + c] = uv;
        }
        __syncthreads();

        // ---- S = Q K^T ----
        float s[8][4];
#pragma unroll
        for (int nb = 0; nb < 8; nb++) {
            s[nb][0] = s[nb][1] = s[nb][2] = s[nb][3] = 0.f;
#pragma unroll
            for (int kk = 0; kk < 8; kk++) {
                uint32_t b0 = Ks[(nb * 8 + g) * SPITCH + kk * 8 + tig];
                uint32_t b1 = Ks[(nb * 8 + g) * SPITCH + kk * 8 + tig + 4];
                mma_tf32(s[nb], qa[kk][0], qa[kk][1], qa[kk][2], qa[kk][3], b0, b1);
            }
        }

        // ---- Causal mask (diagonal tile only) ----
        if (kt == qt) {
#pragma unroll
            for (int nb = 0; nb < 8; nb++) {
                int kc = nb * 8 + 2 * tig;
                int r0 = rw + g, r1 = rw + g + 8;
                if (kc     > r0) s[nb][0] = -1e30f;
                if (kc + 1 > r0) s[nb][1] = -1e30f;
                if (kc     > r1) s[nb][2] = -1e30f;
                if (kc + 1 > r1) s[nb][3] = -1e30f;
            }
        }

        // ---- Online softmax ----
        float tm0 = -1e30f, tm1 = -1e30f;
#pragma unroll
        for (int nb = 0; nb < 8; nb++) {
            tm0 = fmaxf(tm0, fmaxf(s[nb][0], s[nb][1]));
            tm1 = fmaxf(tm1, fmaxf(s[nb][2], s[nb][3]));
        }
        tm0 = fmaxf(tm0, __shfl_xor_sync(0xffffffffu, tm0, 1));
        tm0 = fmaxf(tm0, __shfl_xor_sync(0xffffffffu, tm0, 2));
        tm1 = fmaxf(tm1, __shfl_xor_sync(0xffffffffu, tm1, 1));
        tm1 = fmaxf(tm1, __shfl_xor_sync(0xffffffffu, tm1, 2));

        float mn0 = fmaxf(m0, tm0), mn1 = fmaxf(m1, tm1);
        float a0 = __expf(m0 - mn0), a1 = __expf(m1 - mn1);
        l0 *= a0; l1 *= a1;
#pragma unroll
        for (int nb = 0; nb < 8; nb++) {
            O[nb][0] *= a0; O[nb][1] *= a0;
            O[nb][2] *= a1; O[nb][3] *= a1;
        }

        float rs0 = 0.f, rs1 = 0.f;
#pragma unroll
        for (int nb = 0; nb < 8; nb++) {
            float p0 = __expf(s[nb][0] - mn0);
            float p1 = __expf(s[nb][1] - mn0);
            float p2 = __expf(s[nb][2] - mn1);
            float p3 = __expf(s[nb][3] - mn1);
            rs0 += p0 + p1; rs1 += p2 + p3;
            uint2 u01 = make_uint2(f2tf32(p0), f2tf32(p1));
            uint2 u23 = make_uint2(f2tf32(p2), f2tf32(p3));
            *(uint2*)&Ps[(rw + g)     * SPITCH + nb * 8 + 2 * tig] = u01;
            *(uint2*)&Ps[(rw + g + 8) * SPITCH + nb * 8 + 2 * tig] = u23;
        }
        rs0 += __shfl_xor_sync(0xffffffffu, rs0, 1);
        rs0 += __shfl_xor_sync(0xffffffffu, rs0, 2);
        rs1 += __shfl_xor_sync(0xffffffffu, rs1, 1);
        rs1 += __shfl_xor_sync(0xffffffffu, rs1, 2);
        l0 += rs0; l1 += rs1;
        m0 = mn0; m1 = mn1;

        __syncwarp();

        // ---- O += P V ----
#pragma unroll
        for (int kk = 0; kk < 8; kk++) {
            uint32_t pa0 = Ps[(rw + g)     * SPITCH + kk * 8 + tig];
            uint32_t pa1 = Ps[(rw + g + 8) * SPITCH + kk * 8 + tig];
            uint32_t pa2 = Ps[(rw + g)     * SPITCH + kk * 8 + tig + 4];
            uint32_t pa3 = Ps[(rw + g + 8) * SPITCH + kk * 8 + tig + 4];
#pragma unroll
            for (int nb = 0; nb < 8; nb++) {
                uint32_t b0 = Vs[(kk * 8 + tig)     * SPITCH + nb * 8 + g];
                uint32_t b1 = Vs[(kk * 8 + tig + 4) * SPITCH + nb * 8 + g];
                mma_tf32(O[nb], pa0, pa1, pa2, pa3, b0, b1);
            }
        }
        __syncwarp();
    }

    // ---- Epilogue ----
    float inv0 = 1.f / l0, inv1 = 1.f / l1;
    int r0 = qrow0 + rw + g;
    int r1 = r0 + 8;
#pragma unroll
    for (int nb = 0; nb < 8; nb++) {
        int c = nb * 8 + 2 * tig;
        float2 v0 = make_float2(O[nb][0] * inv0, O[nb][1] * inv0);
        float2 v1 = make_float2(O[nb][2] * inv1, O[nb][3] * inv1);
        *(float2*)(Y + base + (size_t)r0 * CDIM + c) = v0;
        *(float2*)(Y + base + (size_t)r1 * CDIM + c) = v1;
    }
}

// ---------------------------------------------------------------------------
// Launch: fused QKV GEMM -> attention -> output GEMM
// ---------------------------------------------------------------------------
extern "C" void kernel_launch(void* const* d_in, const int* in_sizes, int n_in,
                              void* d_out, int out_size)
{
    const float* x  = (const float*)d_in[0];
    const float* Wq = (const float*)d_in[1];
    const float* bq = (const float*)d_in[2];
    const float* Wk = (const float*)d_in[3];
    const float* bk = (const float*)d_in[4];
    const float* Wv = (const float*)d_in[5];
    const float* bv = (const float*)d_in[6];
    const float* Wp = (const float*)d_in[7];
    const float* bp = (const float*)d_in[8];
    float* out = (float*)d_out;

    float *Qb, *Kb, *Vb, *Yb;
    cudaGetSymbolAddress((void**)&Qb, g_Q);
    cudaGetSymbolAddress((void**)&Kb, g_K);
    cudaGetSymbolAddress((void**)&Vb, g_V);
    cudaGetSymbolAddress((void**)&Yb, g_Y);

    dim3 blk(128);

    // Fused Q/K/V projections: grid.z picks the weight/output triple
    dim3 qkvGrid(CDIM / BN, MROWS / BM, 3);   // (8, 64, 3)
    gemm_tf32_pipe<<<qkvGrid, blk>>>(x,
                                     Wq, bq, Qb,
                                     Wk, bk, Kb,
                                     Wv, bv, Vb,
                                     MROWS, CDIM, CDIM);

    dim3 aGrid(SEQ / 64, BATCH * N_HEADS);    // (32, 64)
    attn_mma_kernel<<<aGrid, dim3(128)>>>(Qb, Kb, Vb, Yb);

    // Output projection
    dim3 pGrid(CDIM / BN, MROWS / BM, 1);
    gemm_tf32_pipe<<<pGrid, blk>>>(Yb,
                                   Wp, bp, out,
                                   Wp, bp, out,
                                   Wp, bp, out,
                                   MROWS, CDIM, CDIM);
}

// round 7
// speedup vs baseline: 6.4608x; 1.0709x over previous
#include <cuda_runtime.h>
#include <cstdint>
#include <cstddef>

// Problem constants
#define N_HEADS 16
#define BATCH   4
#define SEQ     2048
#define CDIM    1024
#define HDIM    64
#define MROWS   (BATCH * SEQ)   // 8192

// ---------------------------------------------------------------------------
// Scratch (device globals: allocation-free rule)
// ---------------------------------------------------------------------------
__device__ float g_Q[(size_t)MROWS * CDIM];
__device__ float g_K[(size_t)MROWS * CDIM];
__device__ float g_V[(size_t)MROWS * CDIM];
__device__ float g_Y[(size_t)MROWS * CDIM];

// ---------------------------------------------------------------------------
// tf32 helpers
// ---------------------------------------------------------------------------
__device__ __forceinline__ uint32_t f2tf32(float x) {
    uint32_t r;
    asm("cvt.rna.tf32.f32 %0, %1;" : "=r"(r) : "f"(x));
    return r;
}

__device__ __forceinline__ void mma_tf32(float* d, uint32_t a0, uint32_t a1,
                                         uint32_t a2, uint32_t a3,
                                         uint32_t b0, uint32_t b1) {
    asm volatile(
        "mma.sync.aligned.m16n8k8.row.col.f32.tf32.tf32.f32 "
        "{%0,%1,%2,%3}, {%4,%5,%6,%7}, {%8,%9}, {%0,%1,%2,%3};\n"
        : "+f"(d[0]), "+f"(d[1]), "+f"(d[2]), "+f"(d[3])
        : "r"(a0), "r"(a1), "r"(a2), "r"(a3), "r"(b0), "r"(b1));
}

// ---------------------------------------------------------------------------
// Pipelined GEMM (unchanged from round 6): BM=BN=128, BK=16, 128 threads,
// 2x2 warp grid of 64x64 tiles, double-buffered smem + register prefetch.
// ---------------------------------------------------------------------------
#define BM 128
#define BN 128
#define BKK 16
#define APAD 20
#define BPAD 136

__global__ __launch_bounds__(128, 2)
void gemm_tf32_pipe(const float* __restrict__ A,
                    const float* __restrict__ Wa, const float* __restrict__ ba,
                    float* __restrict__ Ca,
                    const float* __restrict__ Wb, const float* __restrict__ bb,
                    float* __restrict__ Cb,
                    const float* __restrict__ Wc, const float* __restrict__ bc,
                    float* __restrict__ Cc,
                    int M, int Ntot, int K)
{
    const int z = blockIdx.z;
    const float* W    = (z == 0) ? Wa : (z == 1) ? Wb : Wc;
    const float* bias = (z == 0) ? ba : (z == 1) ? bb : bc;
    float*       C    = (z == 0) ? Ca : (z == 1) ? Cb : Cc;

    __shared__ uint32_t As[2][BM * APAD];
    __shared__ uint32_t Bs[2][BKK * BPAD];

    const int tid  = threadIdx.x;
    const int lane = tid & 31;
    const int warp = tid >> 5;
    const int g    = lane >> 2;
    const int tig  = lane & 3;
    const int wm   = warp & 1;
    const int wn   = warp >> 1;
    const int bM   = blockIdx.y * BM;
    const int bN   = blockIdx.x * BN;

    const float* pA[4]; const float* pB[4];
    int sA[4], sB[4];
#pragma unroll
    for (int j = 0; j < 4; j++) {
        int idx = tid + j * 128;
        int rA = idx >> 2,  cA = (idx & 3) << 2;
        int rB = idx >> 5,  cB = (idx & 31) << 2;
        pA[j] = A + (size_t)(bM + rA) * K + cA;
        pB[j] = W + (size_t)rB * Ntot + bN + cB;
        sA[j] = rA * APAD + cA;
        sB[j] = rB * BPAD + cB;
    }

    float acc[4][8][4];
#pragma unroll
    for (int im = 0; im < 4; im++)
#pragma unroll
        for (int nb = 0; nb < 8; nb++)
#pragma unroll
            for (int j = 0; j < 4; j++) acc[im][nb][j] = 0.f;

#pragma unroll
    for (int j = 0; j < 4; j++) {
        float4 a = *(const float4*)pA[j];
        float4 b = *(const float4*)pB[j];
        uint32_t* d;
        d = &As[0][sA[j]]; d[0]=f2tf32(a.x); d[1]=f2tf32(a.y); d[2]=f2tf32(a.z); d[3]=f2tf32(a.w);
        d = &Bs[0][sB[j]]; d[0]=f2tf32(b.x); d[1]=f2tf32(b.y); d[2]=f2tf32(b.z); d[3]=f2tf32(b.w);
    }
    __syncthreads();

    const int nTiles = K / BKK;
    for (int t = 0; t < nTiles; t++) {
        const int buf = t & 1;
        const bool has = (t + 1) < nTiles;

        float4 fa[4], fb[4];
        if (has) {
            const int ko = (t + 1) * BKK;
#pragma unroll
            for (int j = 0; j < 4; j++) {
                fa[j] = *(const float4*)(pA[j] + ko);
                fb[j] = *(const float4*)(pB[j] + (size_t)ko * Ntot);
            }
        }

#pragma unroll
        for (int kk = 0; kk < BKK; kk += 8) {
            uint32_t af[4][4];
#pragma unroll
            for (int im = 0; im < 4; im++) {
                int rb = wm * 64 + im * 16;
                af[im][0] = As[buf][(rb + g)     * APAD + kk + tig];
                af[im][1] = As[buf][(rb + g + 8) * APAD + kk + tig];
                af[im][2] = As[buf][(rb + g)     * APAD + kk + tig + 4];
                af[im][3] = As[buf][(rb + g + 8) * APAD + kk + tig + 4];
            }
            uint32_t bf[8][2];
#pragma unroll
            for (int nb = 0; nb < 8; nb++) {
                int cb = wn * 64 + nb * 8 + g;
                bf[nb][0] = Bs[buf][(kk + tig)     * BPAD + cb];
                bf[nb][1] = Bs[buf][(kk + tig + 4) * BPAD + cb];
            }
#pragma unroll
            for (int im = 0; im < 4; im++)
#pragma unroll
                for (int nb = 0; nb < 8; nb++)
                    mma_tf32(acc[im][nb], af[im][0], af[im][1], af[im][2], af[im][3],
                             bf[nb][0], bf[nb][1]);
        }

        if (has) {
            const int nxt = buf ^ 1;
#pragma unroll
            for (int j = 0; j < 4; j++) {
                uint32_t* d;
                d = &As[nxt][sA[j]]; d[0]=f2tf32(fa[j].x); d[1]=f2tf32(fa[j].y); d[2]=f2tf32(fa[j].z); d[3]=f2tf32(fa[j].w);
                d = &Bs[nxt][sB[j]]; d[0]=f2tf32(fb[j].x); d[1]=f2tf32(fb[j].y); d[2]=f2tf32(fb[j].z); d[3]=f2tf32(fb[j].w);
            }
            __syncthreads();
        }
    }

#pragma unroll
    for (int im = 0; im < 4; im++) {
        int r0 = bM + wm * 64 + im * 16 + g;
#pragma unroll
        for (int nb = 0; nb < 8; nb++) {
            int c = bN + wn * 64 + nb * 8 + 2 * tig;
            float bv0 = bias[c], bv1 = bias[c + 1];
            float2 v0 = make_float2(acc[im][nb][0] + bv0, acc[im][nb][1] + bv1);
            float2 v1 = make_float2(acc[im][nb][2] + bv0, acc[im][nb][3] + bv1);
            *(float2*)(C + (size_t)r0       * Ntot + c) = v0;
            *(float2*)(C + (size_t)(r0 + 8) * Ntot + c) = v1;
        }
    }
}

// ---------------------------------------------------------------------------
// Tensor-core causal flash attention, 128 q-rows per block.
// 4 warps x 32 q-rows each: every K/V fragment LDS now feeds 2x the MMAs
// (4B/MMA S-pass, 6B/MMA PV-pass vs 8/10 before) — attacks the measured
// L1=76% / tensor=30% crossbar bound. Dynamic smem 69.6KB, 2 blocks/SM.
// ---------------------------------------------------------------------------
#define SPITCH 68
#define ATTN_SMEM_BYTES ((64 * SPITCH * 2 + 128 * SPITCH) * 4)  // 69632

__global__ __launch_bounds__(128, 2)
void attn_mma_kernel(const float* __restrict__ Q, const float* __restrict__ K,
                     const float* __restrict__ V, float* __restrict__ Y)
{
    extern __shared__ uint32_t dsm[];
    uint32_t* Ks = dsm;                      // 64 x SPITCH
    uint32_t* Vs = Ks + 64 * SPITCH;         // 64 x SPITCH
    uint32_t* Ps = Vs + 64 * SPITCH;         // 128 x SPITCH (Q stage, then P)

    const int tid  = threadIdx.x;
    const int lane = tid & 31;
    const int warp = tid >> 5;
    const int g    = lane >> 2;
    const int tig  = lane & 3;
    const int rw   = warp * 32;              // warp's q-row base (32 rows)

    const int qt = 15 - blockIdx.x;          // heavy tiles first
    const int bh = blockIdx.y;
    const int b  = bh >> 4;
    const int h  = bh & 15;
    const int qrow0 = qt * 128;

    const size_t base = (size_t)b * SEQ * CDIM + (size_t)h * HDIM;

    // ---- Stage Q tile (128 x 64, scaled, tf32) into Ps ----
    {
        const float scale = 0.125f;  // 1/sqrt(64)
#pragma unroll
        for (int j = 0; j < 16; j++) {
            int idx = tid + j * 128;         // 2048 float4 slots
            int r = idx >> 4;
            int c = (idx & 15) << 2;
            float4 v = *(const float4*)(Q + base + (size_t)(qrow0 + r) * CDIM + c);
            uint4 u;
            u.x = f2tf32(v.x * scale); u.y = f2tf32(v.y * scale);
            u.z = f2tf32(v.z * scale); u.w = f2tf32(v.w * scale);
            *(uint4*)&Ps[r * SPITCH + c] = u;
        }
    }
    __syncthreads();

    // ---- Persistent Q A-fragments: 2 m16 tiles x 8 kk x 4 regs ----
    uint32_t qa[2][8][4];
#pragma unroll
    for (int im = 0; im < 2; im++)
#pragma unroll
        for (int kk = 0; kk < 8; kk++) {
            int r0 = rw + im * 16 + g;
            qa[im][kk][0] = Ps[(r0)     * SPITCH + kk * 8 + tig];
            qa[im][kk][1] = Ps[(r0 + 8) * SPITCH + kk * 8 + tig];
            qa[im][kk][2] = Ps[(r0)     * SPITCH + kk * 8 + tig + 4];
            qa[im][kk][3] = Ps[(r0 + 8) * SPITCH + kk * 8 + tig + 4];
        }

    float O[2][8][4];
#pragma unroll
    for (int im = 0; im < 2; im++)
#pragma unroll
        for (int nb = 0; nb < 8; nb++)
#pragma unroll
            for (int j = 0; j < 4; j++) O[im][nb][j] = 0.f;
    float mm[2][2], ll[2][2];
#pragma unroll
    for (int im = 0; im < 2; im++) {
        mm[im][0] = mm[im][1] = -1e30f;
        ll[im][0] = ll[im][1] = 0.f;
    }

    const int nkt = 2 * qt + 2;   // 64-key tiles covering keys <= qrow0+127
    for (int kt = 0; kt < nkt; kt++) {
        __syncthreads();   // prior PV reads of Ks/Vs done; qa reads done (kt=0)
        // ---- Load K and V tiles (64 x 64) as tf32 ----
#pragma unroll
        for (int j = 0; j < 8; j++) {
            int idx = tid + j * 128;
            int r = idx >> 4;
            int c = (idx & 15) << 2;
            size_t goff = base + (size_t)(kt * 64 + r) * CDIM + c;
            float4 kv = *(const float4*)(K + goff);
            float4 vv = *(const float4*)(V + goff);
            uint4 uk, uv;
            uk.x = f2tf32(kv.x); uk.y = f2tf32(kv.y);
            uk.z = f2tf32(kv.z); uk.w = f2tf32(kv.w);
            uv.x = f2tf32(vv.x); uv.y = f2tf32(vv.y);
            uv.z = f2tf32(vv.z); uv.w = f2tf32(vv.w);
            *(uint4*)&Ks[r * SPITCH + c] = uk;
            *(uint4*)&Vs[r * SPITCH + c] = uv;
        }
        __syncthreads();

        // ---- S = Q K^T : 2 im x 8 nb tiles; K-frags shared across im ----
        float s[2][8][4];
#pragma unroll
        for (int im = 0; im < 2; im++)
#pragma unroll
            for (int nb = 0; nb < 8; nb++)
                s[im][nb][0] = s[im][nb][1] = s[im][nb][2] = s[im][nb][3] = 0.f;
#pragma unroll
        for (int kk = 0; kk < 8; kk++) {
            uint32_t bf[8][2];
#pragma unroll
            for (int nb = 0; nb < 8; nb++) {
                bf[nb][0] = Ks[(nb * 8 + g) * SPITCH + kk * 8 + tig];
                bf[nb][1] = Ks[(nb * 8 + g) * SPITCH + kk * 8 + tig + 4];
            }
#pragma unroll
            for (int im = 0; im < 2; im++)
#pragma unroll
                for (int nb = 0; nb < 8; nb++)
                    mma_tf32(s[im][nb], qa[im][kk][0], qa[im][kk][1],
                             qa[im][kk][2], qa[im][kk][3], bf[nb][0], bf[nb][1]);
        }

        // ---- Causal mask (last two tiles cross the diagonal) ----
        if (kt >= nkt - 2) {
#pragma unroll
            for (int im = 0; im < 2; im++) {
                int r0 = qrow0 + rw + im * 16 + g;   // absolute q rows
                int r1 = r0 + 8;
#pragma unroll
                for (int nb = 0; nb < 8; nb++) {
                    int kg = kt * 64 + nb * 8 + 2 * tig;  // absolute key
                    if (kg     > r0) s[im][nb][0] = -1e30f;
                    if (kg + 1 > r0) s[im][nb][1] = -1e30f;
                    if (kg     > r1) s[im][nb][2] = -1e30f;
                    if (kg + 1 > r1) s[im][nb][3] = -1e30f;
                }
            }
        }

        // ---- Online softmax + P store (per im, rows g and g+8) ----
#pragma unroll
        for (int im = 0; im < 2; im++) {
            float tm0 = -1e30f, tm1 = -1e30f;
#pragma unroll
            for (int nb = 0; nb < 8; nb++) {
                tm0 = fmaxf(tm0, fmaxf(s[im][nb][0], s[im][nb][1]));
                tm1 = fmaxf(tm1, fmaxf(s[im][nb][2], s[im][nb][3]));
            }
            tm0 = fmaxf(tm0, __shfl_xor_sync(0xffffffffu, tm0, 1));
            tm0 = fmaxf(tm0, __shfl_xor_sync(0xffffffffu, tm0, 2));
            tm1 = fmaxf(tm1, __shfl_xor_sync(0xffffffffu, tm1, 1));
            tm1 = fmaxf(tm1, __shfl_xor_sync(0xffffffffu, tm1, 2));

            float mn0 = fmaxf(mm[im][0], tm0), mn1 = fmaxf(mm[im][1], tm1);
            float a0 = __expf(mm[im][0] - mn0), a1 = __expf(mm[im][1] - mn1);
            ll[im][0] *= a0; ll[im][1] *= a1;
#pragma unroll
            for (int nb = 0; nb < 8; nb++) {
                O[im][nb][0] *= a0; O[im][nb][1] *= a0;
                O[im][nb][2] *= a1; O[im][nb][3] *= a1;
            }

            float rs0 = 0.f, rs1 = 0.f;
            int r0 = rw + im * 16 + g;
#pragma unroll
            for (int nb = 0; nb < 8; nb++) {
                float p0 = __expf(s[im][nb][0] - mn0);
                float p1 = __expf(s[im][nb][1] - mn0);
                float p2 = __expf(s[im][nb][2] - mn1);
                float p3 = __expf(s[im][nb][3] - mn1);
                rs0 += p0 + p1; rs1 += p2 + p3;
                uint2 u01 = make_uint2(f2tf32(p0), f2tf32(p1));
                uint2 u23 = make_uint2(f2tf32(p2), f2tf32(p3));
                *(uint2*)&Ps[(r0)     * SPITCH + nb * 8 + 2 * tig] = u01;
                *(uint2*)&Ps[(r0 + 8) * SPITCH + nb * 8 + 2 * tig] = u23;
            }
            rs0 += __shfl_xor_sync(0xffffffffu, rs0, 1);
            rs0 += __shfl_xor_sync(0xffffffffu, rs0, 2);
            rs1 += __shfl_xor_sync(0xffffffffu, rs1, 1);
            rs1 += __shfl_xor_sync(0xffffffffu, rs1, 2);
            ll[im][0] += rs0; ll[im][1] += rs1;
            mm[im][0] = mn0; mm[im][1] = mn1;
        }
        __syncwarp();

        // ---- O += P V : V-frags shared across im ----
#pragma unroll
        for (int kk = 0; kk < 8; kk++) {
            uint32_t pa[2][4];
#pragma unroll
            for (int im = 0; im < 2; im++) {
                int r0 = rw + im * 16 + g;
                pa[im][0] = Ps[(r0)     * SPITCH + kk * 8 + tig];
                pa[im][1] = Ps[(r0 + 8) * SPITCH + kk * 8 + tig];
                pa[im][2] = Ps[(r0)     * SPITCH + kk * 8 + tig + 4];
                pa[im][3] = Ps[(r0 + 8) * SPITCH + kk * 8 + tig + 4];
            }
            uint32_t bf[8][2];
#pragma unroll
            for (int nb = 0; nb < 8; nb++) {
                bf[nb][0] = Vs[(kk * 8 + tig)     * SPITCH + nb * 8 + g];
                bf[nb][1] = Vs[(kk * 8 + tig + 4) * SPITCH + nb * 8 + g];
            }
#pragma unroll
            for (int im = 0; im < 2; im++)
#pragma unroll
                for (int nb = 0; nb < 8; nb++)
                    mma_tf32(O[im][nb], pa[im][0], pa[im][1], pa[im][2], pa[im][3],
                             bf[nb][0], bf[nb][1]);
        }
        __syncwarp();   // P reads done before next iteration's P stores
    }

    // ---- Epilogue: normalize and store ----
#pragma unroll
    for (int im = 0; im < 2; im++) {
        float inv0 = 1.f / ll[im][0], inv1 = 1.f / ll[im][1];
        int r0 = qrow0 + rw + im * 16 + g;
        int r1 = r0 + 8;
#pragma unroll
        for (int nb = 0; nb < 8; nb++) {
            int c = nb * 8 + 2 * tig;
            float2 v0 = make_float2(O[im][nb][0] * inv0, O[im][nb][1] * inv0);
            float2 v1 = make_float2(O[im][nb][2] * inv1, O[im][nb][3] * inv1);
            *(float2*)(Y + base + (size_t)r0 * CDIM + c) = v0;
            *(float2*)(Y + base + (size_t)r1 * CDIM + c) = v1;
        }
    }
}

// ---------------------------------------------------------------------------
// Launch: fused QKV GEMM -> attention -> output GEMM
// ---------------------------------------------------------------------------
extern "C" void kernel_launch(void* const* d_in, const int* in_sizes, int n_in,
                              void* d_out, int out_size)
{
    const float* x  = (const float*)d_in[0];
    const float* Wq = (const float*)d_in[1];
    const float* bq = (const float*)d_in[2];
    const float* Wk = (const float*)d_in[3];
    const float* bk = (const float*)d_in[4];
    const float* Wv = (const float*)d_in[5];
    const float* bv = (const float*)d_in[6];
    const float* Wp = (const float*)d_in[7];
    const float* bp = (const float*)d_in[8];
    float* out = (float*)d_out;

    float *Qb, *Kb, *Vb, *Yb;
    cudaGetSymbolAddress((void**)&Qb, g_Q);
    cudaGetSymbolAddress((void**)&Kb, g_K);
    cudaGetSymbolAddress((void**)&Vb, g_V);
    cudaGetSymbolAddress((void**)&Yb, g_Y);

    cudaFuncSetAttribute(attn_mma_kernel,
                         cudaFuncAttributeMaxDynamicSharedMemorySize,
                         ATTN_SMEM_BYTES);

    dim3 blk(128);

    // Fused Q/K/V projections: grid.z picks the weight/output triple
    dim3 qkvGrid(CDIM / BN, MROWS / BM, 3);   // (8, 64, 3)
    gemm_tf32_pipe<<<qkvGrid, blk>>>(x,
                                     Wq, bq, Qb,
                                     Wk, bk, Kb,
                                     Wv, bv, Vb,
                                     MROWS, CDIM, CDIM);

    dim3 aGrid(SEQ / 128, BATCH * N_HEADS);   // (16, 64)
    attn_mma_kernel<<<aGrid, blk, ATTN_SMEM_BYTES>>>(Qb, Kb, Vb, Yb);

    // Output projection
    dim3 pGrid(CDIM / BN, MROWS / BM, 1);
    gemm_tf32_pipe<<<pGrid, blk>>>(Yb,
                                   Wp, bp, out,
                                   Wp, bp, out,
                                   Wp, bp, out,
                                   MROWS, CDIM, CDIM);
}